// round 10
// baseline (speedup 1.0000x reference)
#include <cuda_runtime.h>
#include <cuda_bf16.h>

#define FULL_MASK 0xFFFFFFFFu
#define WPB 8          // warps per block (render)
#define NMAX 65536

// Segment start offsets: g_start[r] = first sample of ray r, g_start[N] = M.
__device__ int g_start[NMAX + 1];

__device__ __forceinline__ float tanh_fast(float x) {
    float y;
    asm("tanh.approx.f32 %0, %1;" : "=f"(y) : "f"(x));
    return y;
}
// sigmoid(x) = 0.5*tanh(0.5x) + 0.5  (single MUFU)
__device__ __forceinline__ float sigmoid_fast(float x) {
    return fmaf(tanh_fast(0.5f * x), 0.5f, 0.5f);
}

// ---------------------------------------------------------------------------
// Kernel 1: boundary detection over the sorted ray_id array (int4 per thread).
// Writes g_start[r] for every boundary (covers empty rays); the tail thread
// fills g_start[last+1 .. N] = M.
// ---------------------------------------------------------------------------
__global__ void __launch_bounds__(256)
boundary_kernel(const int* __restrict__ ray_id, int M, int N)
{
    const int t = blockIdx.x * blockDim.x + threadIdx.x;
    const int i = t * 4;
    if (i >= M) return;

    if (i + 4 <= M) {
        const int4 v = *(const int4*)(ray_id + i);
        const int a = (i == 0) ? -1 : __ldg(ray_id + i - 1);
        if (a   != v.x) for (int r = a   + 1; r <= v.x; r++) g_start[r] = i;
        if (v.x != v.y) for (int r = v.x + 1; r <= v.y; r++) g_start[r] = i + 1;
        if (v.y != v.z) for (int r = v.y + 1; r <= v.z; r++) g_start[r] = i + 2;
        if (v.z != v.w) for (int r = v.z + 1; r <= v.w; r++) g_start[r] = i + 3;
        if (i + 4 == M)
            for (int r = v.w + 1; r <= N; r++) g_start[r] = M;
    } else {
        int a = (i == 0) ? -1 : __ldg(ray_id + i - 1);
        for (int j = i; j < M; j++) {
            int b = __ldg(ray_id + j);
            if (a != b) for (int r = a + 1; r <= b; r++) g_start[r] = j;
            a = b;
        }
        for (int r = a + 1; r <= N; r++) g_start[r] = M;
    }
}

// ---------------------------------------------------------------------------
// Kernel 2: one warp per ray, interleaved K=4 layout (lane j owns samples
// [base + 4*lane, +4) of each 128-sample chunk -> perfectly coalesced
// float4 loads). Next chunk's loads are prefetched (warp-uniform guard)
// before computing the current one. Colors are folded into lane-local
// weighted sums before the per-chunk warp product scan; `carry` links chunks.
//
// Math (interval = 0.5):
//   t  = density*log2(e) + shift*log2(e)      (invalid sample -> t = -200)
//   ex = 2^t,  om = rsqrt(1+ex) = exp(-0.5*softplus(x))
//   alpha = 1 - om   (exact where it matters; ~1e-7 abs noise where alpha tiny)
//   alphainv_last = final carry
// ---------------------------------------------------------------------------
__global__ void __launch_bounds__(WPB * 32)
render_kernel(const float* __restrict__ density,
              const float* __restrict__ rgb_raw,
              const float* __restrict__ shift,
              float*       __restrict__ out,
              int M, int N)
{
    const int warp = blockIdx.x * WPB + (threadIdx.x >> 5);
    if (warp >= N) return;
    const int lane = threadIdx.x & 31;

    const float L2E  = 1.4426950408889634f;
    const float shl  = __ldg(shift) * L2E;

    const int start = g_start[warp];
    const int end   = g_start[warp + 1];
    const int a0    = start & ~3;               // 4-aligned loop base
    const unsigned len = (unsigned)(end - start);

    float carry = 1.0f;
    float accR = 0.f, accG = 0.f, accB = 0.f;

    if (a0 < end) {
        const int bmax = M - 4;                 // highest legal float4 base
        int b = a0 + 4 * lane;                  // this lane's sample base

        int cb = min(b, bmax);                  // clamp keeps loads in-bounds;
        float4 d4 = __ldcs((const float4*)(density + cb));   // bad lanes masked
        const float4* rp = (const float4*)(rgb_raw + 3 * cb);
        float4 r0 = __ldcs(rp + 0);
        float4 r1 = __ldcs(rp + 1);
        float4 r2 = __ldcs(rp + 2);

        for (int itb = a0; itb < end; itb += 128) {
            const bool more = (itb + 128) < end;        // warp-uniform
            float4 nd4, nr0, nr1, nr2;
            if (more) {                                  // prefetch next chunk
                const int nb = min(b + 128, bmax);
                nd4 = __ldcs((const float4*)(density + nb));
                const float4* nrp = (const float4*)(rgb_raw + 3 * nb);
                nr0 = __ldcs(nrp + 0);
                nr1 = __ldcs(nrp + 1);
                nr2 = __ldcs(nrp + 2);
            }

            const float dv[4]  = { d4.x, d4.y, d4.z, d4.w };
            const float cc[12] = { r0.x, r0.y, r0.z, r0.w, r1.x, r1.y,
                                   r1.z, r1.w, r2.x, r2.y, r2.z, r2.w };

            float q = 1.0f;                     // lane-local product of om
            float vR = 0.f, vG = 0.f, vB = 0.f;
            #pragma unroll
            for (int j = 0; j < 4; ++j) {
                const bool valid = (unsigned)(b + j - start) < len;
                float t = fmaf(dv[j], L2E, shl);
                t = valid ? t : -200.0f;        // 2^-200 = 0 -> om=1, alpha=0
                const float ex = exp2f(t);
                const float o  = rsqrtf(1.0f + ex);   // om = exp(-s)
                const float al = 1.0f - o;            // alpha
                const float w  = al * q;
                vR = fmaf(w, sigmoid_fast(cc[3*j + 0]), vR);
                vG = fmaf(w, sigmoid_fast(cc[3*j + 1]), vG);
                vB = fmaf(w, sigmoid_fast(cc[3*j + 2]), vB);
                q *= o;
            }

            // warp inclusive product scan of q
            float p = q;
            #pragma unroll
            for (int dd = 1; dd < 32; dd <<= 1) {
                const float s = __shfl_up_sync(FULL_MASK, p, dd);
                if (lane >= dd) p *= s;
            }
            float excl = __shfl_up_sync(FULL_MASK, p, 1);
            if (lane == 0) excl = 1.0f;
            const float tot = __shfl_sync(FULL_MASK, p, 31);

            const float t0 = carry * excl;      // transmittance entering lane
            accR = fmaf(t0, vR, accR);
            accG = fmaf(t0, vG, accG);
            accB = fmaf(t0, vB, accB);
            carry *= tot;

            if (more) { d4 = nd4; r0 = nr0; r1 = nr1; r2 = nr2; b += 128; }
        }
    }

    // warp reduction of the color accumulators
    #pragma unroll
    for (int dd = 16; dd >= 1; dd >>= 1) {
        accR += __shfl_xor_sync(FULL_MASK, accR, dd);
        accG += __shfl_xor_sync(FULL_MASK, accG, dd);
        accB += __shfl_xor_sync(FULL_MASK, accB, dd);
    }

    if (lane == 0) {
        out[3 * warp + 0] = accR + carry;       // white background leftover
        out[3 * warp + 1] = accG + carry;
        out[3 * warp + 2] = accB + carry;
    }
}

extern "C" void kernel_launch(void* const* d_in, const int* in_sizes, int n_in,
                              void* d_out, int out_size)
{
    const float* density = (const float*)d_in[0];
    const float* rgb_raw = (const float*)d_in[1];
    const float* shift   = (const float*)d_in[2];
    const int*   ray_id  = (const int*)d_in[3];
    float*       out     = (float*)d_out;

    const int M = in_sizes[0];
    int N = out_size / 3;
    if (N > NMAX) N = NMAX;

    const int t1 = (M + 3) / 4;
    boundary_kernel<<<(t1 + 255) / 256, 256>>>(ray_id, M, N);

    const int blocks = (N + WPB - 1) / WPB;
    render_kernel<<<blocks, WPB * 32>>>(density, rgb_raw, shift, out, M, N);
}

// round 13
// speedup vs baseline: 1.1068x; 1.1068x over previous
#include <cuda_runtime.h>
#include <cuda_bf16.h>

#define FULL_MASK 0xFFFFFFFFu
#define WPB 4          // warps per block (render)
#define NMAX 65536

// Segment start offsets: g_start[r] = first sample of ray r, g_start[N] = M.
__device__ int g_start[NMAX + 1];

__device__ __forceinline__ float tanh_fast(float x) {
    float y;
    asm("tanh.approx.f32 %0, %1;" : "=f"(y) : "f"(x));
    return y;
}
// sigmoid(x) = 0.5*tanh(0.5x) + 0.5  (single MUFU)
__device__ __forceinline__ float sigmoid_fast(float x) {
    return fmaf(tanh_fast(0.5f * x), 0.5f, 0.5f);
}

// ---------------------------------------------------------------------------
// Kernel 1: boundary detection over the sorted ray_id array (int4 per thread).
// Writes g_start[r] for every boundary (covers empty rays); the tail thread
// fills g_start[last+1 .. N] = M.
// ---------------------------------------------------------------------------
__global__ void __launch_bounds__(256)
boundary_kernel(const int* __restrict__ ray_id, int M, int N)
{
    const int t = blockIdx.x * blockDim.x + threadIdx.x;
    const int i = t * 4;
    if (i >= M) return;

    if (i + 4 <= M) {
        const int4 v = *(const int4*)(ray_id + i);
        const int a = (i == 0) ? -1 : __ldg(ray_id + i - 1);
        if (a   != v.x) for (int r = a   + 1; r <= v.x; r++) g_start[r] = i;
        if (v.x != v.y) for (int r = v.x + 1; r <= v.y; r++) g_start[r] = i + 1;
        if (v.y != v.z) for (int r = v.y + 1; r <= v.z; r++) g_start[r] = i + 2;
        if (v.z != v.w) for (int r = v.z + 1; r <= v.w; r++) g_start[r] = i + 3;
        if (i + 4 == M)
            for (int r = v.w + 1; r <= N; r++) g_start[r] = M;
    } else {
        int a = (i == 0) ? -1 : __ldg(ray_id + i - 1);
        for (int j = i; j < M; j++) {
            int b = __ldg(ray_id + j);
            if (a != b) for (int r = a + 1; r <= b; r++) g_start[r] = j;
            a = b;
        }
        for (int r = a + 1; r <= N; r++) g_start[r] = M;
    }
}

// ---------------------------------------------------------------------------
// Kernel 2: one warp per ray. Interleaved K=4 layout: within each 128-sample
// chunk, lane L owns samples [chunk + 4L, +4) -> float4 loads are perfectly
// coalesced across the warp. Loads are UNCONDITIONAL with a clamped base
// (cb = min(b, M-4)): since M % 4 == 0, any clamped lane has b >= M >= end,
// so all its samples are invalid and masked by the validity select. No
// branches, no zero-init in the loop body.
//
// Math (interval = 0.5):
//   t  = density*log2(e) + shift*log2(e)      (invalid sample -> t = -200)
//   ex = 2^t,  om = rsqrt(1+ex) = exp(-0.5*softplus(x))
//   alpha = 1 - om
//   colors fold into lane-local (vR,vG,vB) weighted by lane-prefix q;
//   one warp product-scan per chunk; `carry` links chunks;
//   alphainv_last = final carry.
// ---------------------------------------------------------------------------
__global__ void __launch_bounds__(WPB * 32)
render_kernel(const float* __restrict__ density,
              const float* __restrict__ rgb_raw,
              const float* __restrict__ shift,
              float*       __restrict__ out,
              int M, int N)
{
    const int warp = blockIdx.x * WPB + (threadIdx.x >> 5);
    if (warp >= N) return;
    const int lane = threadIdx.x & 31;

    const float L2E = 1.4426950408889634f;
    const float shl = __ldg(shift) * L2E;

    const int start = g_start[warp];
    const int end   = g_start[warp + 1];
    const int a0    = start & ~3;               // 4-aligned loop base
    const unsigned len = (unsigned)(end - start);
    const int bmax  = M - 4;                    // highest legal float4 base

    float carry = 1.0f;
    float accR = 0.f, accG = 0.f, accB = 0.f;

    for (int itb = a0; itb < end; itb += 128) {
        const int b  = itb + 4 * lane;          // true sample base of this lane
        const int cb = min(b, bmax);            // clamped load base (in-bounds)

        const float4 d4 = __ldcs((const float4*)(density + cb));
        const float4* rp = (const float4*)(rgb_raw + 3 * cb);
        const float4 r0 = __ldcs(rp + 0);
        const float4 r1 = __ldcs(rp + 1);
        const float4 r2 = __ldcs(rp + 2);

        const float dv[4]  = { d4.x, d4.y, d4.z, d4.w };
        const float cc[12] = { r0.x, r0.y, r0.z, r0.w, r1.x, r1.y,
                               r1.z, r1.w, r2.x, r2.y, r2.z, r2.w };

        float q = 1.0f;                         // lane-local product of om
        float vR = 0.f, vG = 0.f, vB = 0.f;
        #pragma unroll
        for (int j = 0; j < 4; ++j) {
            const bool valid = (unsigned)(b + j - start) < len;
            float t = fmaf(dv[j], L2E, shl);
            t = valid ? t : -200.0f;            // 2^-200 -> ex=0, om=1, alpha=0
            const float ex = exp2f(t);
            const float o  = rsqrtf(1.0f + ex); // om = exp(-s)
            const float w  = (1.0f - o) * q;    // alpha * lane-prefix
            vR = fmaf(w, sigmoid_fast(cc[3*j + 0]), vR);
            vG = fmaf(w, sigmoid_fast(cc[3*j + 1]), vG);
            vB = fmaf(w, sigmoid_fast(cc[3*j + 2]), vB);
            q *= o;
        }

        // warp inclusive product scan of q
        float p = q;
        #pragma unroll
        for (int dd = 1; dd < 32; dd <<= 1) {
            const float s = __shfl_up_sync(FULL_MASK, p, dd);
            if (lane >= dd) p *= s;
        }
        float excl = __shfl_up_sync(FULL_MASK, p, 1);
        if (lane == 0) excl = 1.0f;
        const float tot = __shfl_sync(FULL_MASK, p, 31);

        const float t0 = carry * excl;          // transmittance entering lane
        accR = fmaf(t0, vR, accR);
        accG = fmaf(t0, vG, accG);
        accB = fmaf(t0, vB, accB);
        carry *= tot;
    }

    // warp reduction of the color accumulators
    #pragma unroll
    for (int dd = 16; dd >= 1; dd >>= 1) {
        accR += __shfl_xor_sync(FULL_MASK, accR, dd);
        accG += __shfl_xor_sync(FULL_MASK, accG, dd);
        accB += __shfl_xor_sync(FULL_MASK, accB, dd);
    }

    if (lane == 0) {
        out[3 * warp + 0] = accR + carry;       // white background leftover
        out[3 * warp + 1] = accG + carry;
        out[3 * warp + 2] = accB + carry;
    }
}

extern "C" void kernel_launch(void* const* d_in, const int* in_sizes, int n_in,
                              void* d_out, int out_size)
{
    const float* density = (const float*)d_in[0];
    const float* rgb_raw = (const float*)d_in[1];
    const float* shift   = (const float*)d_in[2];
    const int*   ray_id  = (const int*)d_in[3];
    float*       out     = (float*)d_out;

    const int M = in_sizes[0];
    int N = out_size / 3;
    if (N > NMAX) N = NMAX;

    const int t1 = (M + 3) / 4;
    boundary_kernel<<<(t1 + 255) / 256, 256>>>(ray_id, M, N);

    const int blocks = (N + WPB - 1) / WPB;
    render_kernel<<<blocks, WPB * 32>>>(density, rgb_raw, shift, out, M, N);
}